// round 9
// baseline (speedup 1.0000x reference)
#include <cuda_runtime.h>

#define NN        1024
#define TOTAL_AB  4092
#define RPC       2                  // rows per CTA (64 threads each)
#define FPAD      (NN + (NN >> 5))   // skewed plane size (1056)

typedef unsigned long long u64;

__device__ __forceinline__ int skew(int i) { return i + (i >> 5); }
__device__ __forceinline__ float sigmoidf_(float z) { return 1.0f / (1.0f + expf(-z)); }
__device__ __forceinline__ void rowbar(int id) {
    asm volatile("bar.sync %0, 64;" :: "r"(id) : "memory");
}

// ===================== f32x2 packed helpers (PTX-only) =======================
__device__ __forceinline__ u64 pk2(float x, float y) {
    u64 r; asm("mov.b64 %0,{%1,%2};" : "=l"(r) : "f"(x), "f"(y)); return r;
}
__device__ __forceinline__ float2 upk2(u64 v) {
    float2 r; asm("mov.b64 {%0,%1},%2;" : "=f"(r.x), "=f"(r.y) : "l"(v)); return r;
}
__device__ __forceinline__ u64 dup2(float x) { return pk2(x, x); }
__device__ __forceinline__ u64 swp2(u64 v) {
    u64 r;
    asm("{.reg .f32 a,b; mov.b64 {a,b},%1; mov.b64 %0,{b,a};}" : "=l"(r) : "l"(v));
    return r;
}
__device__ __forceinline__ u64 fma2_(u64 a, u64 b, u64 c) {
    u64 d; asm("fma.rn.f32x2 %0,%1,%2,%3;" : "=l"(d) : "l"(a), "l"(b), "l"(c)); return d;
}
__device__ __forceinline__ u64 mul2_(u64 a, u64 b) {
    u64 d; asm("mul.rn.f32x2 %0,%1,%2;" : "=l"(d) : "l"(a), "l"(b)); return d;
}
__device__ __forceinline__ u64 lerp2(u64 q, u64 x, u64 p, u64 e) {
    return fma2_(q, x, mul2_(p, e));
}

// ================= small perm, REAL, contiguous (16 regs), M=4..16 ===========
template<int M>
__device__ __forceinline__ void perm_small_r(float (&v)[16], float p0, float p1, float p2) {
    const float q0 = 1.0f - p0, q1 = 1.0f - p1, q2 = 1.0f - p2;
#pragma unroll
    for (int jb = 0; jb < 16; jb += M) {
        float todd[M / 2];
#pragma unroll
        for (int k = 0; k < M / 2; ++k) todd[k] = v[jb + 2 * k + 1];
#pragma unroll
        for (int k = 0; k < M / 2; ++k)
            v[jb + k] = q0 * v[jb + k] + p0 * v[jb + 2 * k];
#pragma unroll
        for (int k = 0; k < M / 2; ++k)
            v[jb + M / 2 + k] = q0 * v[jb + M / 2 + k] + p0 * todd[k];
#pragma unroll
        for (int k = 0; k < M / 4; ++k) {
            int a = jb + k, b = jb + M / 2 - 1 - k;
            float va = v[a], vb = v[b];
            v[a] = q1 * va + p1 * vb;  v[b] = q1 * vb + p1 * va;
            int c = jb + M / 2 + k, e = jb + M - 1 - k;
            float vc = v[c], ve = v[e];
            v[c] = q2 * vc + p2 * ve;  v[e] = q2 * ve + p2 * vc;
        }
    }
}

// ================= small perm, PACKED complex, contiguous, M=4..16 ===========
template<int M>
__device__ __forceinline__ void perm_small_p(u64 (&v)[16], u64 q02, u64 p02,
                                             u64 q12, u64 p12, u64 q22, u64 p22) {
#pragma unroll
    for (int jb = 0; jb < 16; jb += M) {
        u64 todd[M / 2];
#pragma unroll
        for (int k = 0; k < M / 2; ++k) todd[k] = v[jb + 2 * k + 1];
#pragma unroll
        for (int k = 0; k < M / 2; ++k)
            v[jb + k] = lerp2(q02, v[jb + k], p02, v[jb + 2 * k]);
#pragma unroll
        for (int k = 0; k < M / 2; ++k)
            v[jb + M / 2 + k] = lerp2(q02, v[jb + M / 2 + k], p02, todd[k]);
#pragma unroll
        for (int k = 0; k < M / 4; ++k) {
            int a = jb + k, b = jb + M / 2 - 1 - k;
            u64 va = v[a], vb = v[b];
            v[a] = lerp2(q12, va, p12, vb);
            v[b] = lerp2(q12, vb, p12, va);
            int c = jb + M / 2 + k, e = jb + M - 1 - k;
            u64 vc = v[c], ve = v[e];
            v[c] = lerp2(q22, vc, p22, ve);
            v[e] = lerp2(q22, ve, p22, vc);
        }
    }
}

// ========== m=32 perm, contiguous thread-pair (t <-> t^1), REAL ==============
// Block of 32 spans threads (even: x[0..15], odd: x[16..31]).
__device__ __forceinline__ void perm32_pair_r(float (&c)[16], int par,
                                              float p0, float p1, float p2) {
    const float q0 = 1.0f - p0;
    float h[8], sv[8];
#pragma unroll
    for (int s = 0; s < 8; ++s) {
        float g = par ? c[2 * s] : c[2 * s + 1];
        h[s] = __shfl_xor_sync(0xffffffffu, g, 1);
        sv[s] = c[2 * s + 1];
    }
#pragma unroll
    for (int j = 0; j < 8; ++j) {
        float e = par ? h[j] : c[2 * j];
        c[j] = q0 * c[j] + p0 * e;
    }
#pragma unroll
    for (int j = 8; j < 16; ++j) {
        float e = par ? sv[j - 8] : h[j - 8];
        c[j] = q0 * c[j] + p0 * e;
    }
    const float pp = par ? p2 : p1, qq = 1.0f - pp;
#pragma unroll
    for (int j = 0; j < 8; ++j) {
        float a = c[j], b = c[15 - j];
        c[j] = qq * a + pp * b;  c[15 - j] = qq * b + pp * a;
    }
}

__device__ __forceinline__ void perm32_pair_p(u64 (&c)[16], int par,
        u64 q02, u64 p02, u64 q12, u64 p12, u64 q22, u64 p22) {
    u64 h[8], sv[8];
#pragma unroll
    for (int s = 0; s < 8; ++s) {
        u64 g = par ? c[2 * s] : c[2 * s + 1];
        h[s] = __shfl_xor_sync(0xffffffffu, g, 1);
        sv[s] = c[2 * s + 1];
    }
#pragma unroll
    for (int j = 0; j < 8; ++j) {
        u64 e = par ? h[j] : c[2 * j];
        c[j] = lerp2(q02, c[j], p02, e);
    }
#pragma unroll
    for (int j = 8; j < 16; ++j) {
        u64 e = par ? sv[j - 8] : h[j - 8];
        c[j] = lerp2(q02, c[j], p02, e);
    }
    const u64 ppk = par ? p22 : p12, qqk = par ? q22 : q12;
#pragma unroll
    for (int j = 0; j < 8; ++j) {
        u64 a = c[j], b = c[15 - j];
        c[j] = lerp2(qqk, a, ppk, b);
        c[15 - j] = lerp2(qqk, b, ppk, a);
    }
}

// ====== large perm M=64..512, REAL, warp-local strided (i = ibase + 32j) =====
// FIRST=true: input regs are contiguous (elem 16t+j); smem pass converts layout.
template<int M, bool FIRST>
__device__ __forceinline__ void sperm_r(float (&v)[16], float* __restrict__ fpl,
                                        int lane, int ibase, int t,
                                        float p0, float p1, float p2) {
    constexpr int M32 = M / 32, H32 = M / 64;
    const float q0 = 1.0f - p0;
    __syncwarp();
    if (FIRST) {
#pragma unroll
        for (int j = 0; j < 16; ++j) fpl[skew(16 * t + j)] = v[j];
    } else {
#pragma unroll
        for (int j = 0; j < 16; ++j) fpl[skew(ibase + 32 * j)] = v[j];
    }
    __syncwarp();
#pragma unroll
    for (int j = 0; j < 16; ++j) {
        int jm = j & (M32 - 1);
        bool hieo = jm >= H32;
        int i = ibase + 32 * j;
        int q = lane + 32 * jm;
        int src = i + q - (hieo ? (M - 1) : 0);
        float xi = FIRST ? fpl[skew(i)] : v[j];
        v[j] = q0 * xi + p0 * fpl[skew(src)];
    }
    const int rl = 31 - lane;
#pragma unroll
    for (int j = 0; j < 16; ++j) {
        int jm = j & (M32 - 1);
        bool hi = jm >= H32;
        int j2 = j - 2 * jm + (hi ? 2 * H32 : 0) + H32 - 1;
        float pp = hi ? p2 : p1, qq = 1.0f - pp;
        if (j2 == j) {
            float a = __shfl_sync(0xffffffffu, v[j], rl);
            v[j] = qq * v[j] + pp * a;
        } else if (j2 > j) {
            float a = __shfl_sync(0xffffffffu, v[j2], rl);
            float b = __shfl_sync(0xffffffffu, v[j],  rl);
            v[j]  = qq * v[j]  + pp * a;
            v[j2] = qq * v[j2] + pp * b;
        }
    }
}

template<int M, bool FIRST>
__device__ __forceinline__ void sperm_p(u64 (&v)[16], u64* __restrict__ pl,
        int lane, int ibase, int t,
        u64 q02, u64 p02, u64 q12, u64 p12, u64 q22, u64 p22) {
    constexpr int M32 = M / 32, H32 = M / 64;
    __syncwarp();
    if (FIRST) {
#pragma unroll
        for (int j = 0; j < 16; ++j) pl[skew(16 * t + j)] = v[j];
    } else {
#pragma unroll
        for (int j = 0; j < 16; ++j) pl[skew(ibase + 32 * j)] = v[j];
    }
    __syncwarp();
#pragma unroll
    for (int j = 0; j < 16; ++j) {
        int jm = j & (M32 - 1);
        bool hieo = jm >= H32;
        int i = ibase + 32 * j;
        int q = lane + 32 * jm;
        int src = i + q - (hieo ? (M - 1) : 0);
        u64 xi = FIRST ? pl[skew(i)] : v[j];
        v[j] = lerp2(q02, xi, p02, pl[skew(src)]);
    }
    const int rl = 31 - lane;
#pragma unroll
    for (int j = 0; j < 16; ++j) {
        int jm = j & (M32 - 1);
        bool hi = jm >= H32;
        int j2 = j - 2 * jm + (hi ? 2 * H32 : 0) + H32 - 1;
        u64 ppk = hi ? p22 : p12, qqk = hi ? q22 : q12;
        if (j2 == j) {
            u64 a = __shfl_sync(0xffffffffu, v[j], rl);
            v[j] = lerp2(qqk, v[j], ppk, a);
        } else if (j2 > j) {
            u64 a = __shfl_sync(0xffffffffu, v[j2], rl);
            u64 b = __shfl_sync(0xffffffffu, v[j],  rl);
            v[j]  = lerp2(qqk, v[j],  ppk, a);
            v[j2] = lerp2(qqk, v[j2], ppk, b);
        }
    }
}

// ====== m=1024 perm: eo cross-warp via smem (row barrier), rev in-warp =======
__device__ __forceinline__ void sperm1024_r(float (&v)[16], float* __restrict__ fpl,
                                            int lane, int w, int ibase, int barid,
                                            float p0, float p1, float p2) {
    const float q0 = 1.0f - p0;
    __syncwarp();
#pragma unroll
    for (int j = 0; j < 16; ++j) fpl[skew(ibase + 32 * j)] = v[j];
    rowbar(barid);
#pragma unroll
    for (int j = 0; j < 16; ++j) {
        int src = 2 * (lane + 32 * j) + w;   // w0 reads evens, w1 reads odds
        v[j] = q0 * v[j] + p0 * fpl[skew(src)];
    }
    rowbar(barid);
    const int rl = 31 - lane;
    const float pp = w ? p2 : p1, qq = 1.0f - pp;
#pragma unroll
    for (int j = 0; j < 8; ++j) {
        float a = __shfl_sync(0xffffffffu, v[15 - j], rl);
        float b = __shfl_sync(0xffffffffu, v[j],      rl);
        v[j]      = qq * v[j]      + pp * a;
        v[15 - j] = qq * v[15 - j] + pp * b;
    }
}

__device__ __forceinline__ void sperm1024_p(u64 (&v)[16], u64* __restrict__ pl,
        int lane, int w, int ibase, int barid,
        u64 q02, u64 p02, u64 q12, u64 p12, u64 q22, u64 p22) {
    __syncwarp();
#pragma unroll
    for (int j = 0; j < 16; ++j) pl[skew(ibase + 32 * j)] = v[j];
    rowbar(barid);
#pragma unroll
    for (int j = 0; j < 16; ++j) {
        int src = 2 * (lane + 32 * j) + w;
        v[j] = lerp2(q02, v[j], p02, pl[skew(src)]);
    }
    rowbar(barid);
    const int rl = 31 - lane;
    const u64 ppk = w ? p22 : p12, qqk = w ? q22 : q12;
#pragma unroll
    for (int j = 0; j < 8; ++j) {
        u64 a = __shfl_sync(0xffffffffu, v[15 - j], rl);
        u64 b = __shfl_sync(0xffffffffu, v[j],      rl);
        v[j]      = lerp2(qqk, v[j],      ppk, a);
        v[15 - j] = lerp2(qqk, v[15 - j], ppk, b);
    }
}

// ======= small diag, PACKED, contiguous, coeffs from smem dup table ==========
template<int M>
__device__ __forceinline__ void diag_small_p(u64 (&v)[16], const u64 (*__restrict__ dup)[8]) {
#pragma unroll
    for (int k = 0; k < M / 2; ++k) {
        const u64 Ax = dup[k][0], Ay = dup[k][1], Bx = dup[k][2], By = dup[k][3];
        const u64 Cx = dup[k][4], Cy = dup[k][5], Dx = dup[k][6], Dy = dup[k][7];
#pragma unroll
        for (int jb = 0; jb < 16; jb += M) {
            u64 x1 = v[jb + k], x2 = v[jb + k + M / 2];
            u64 x1s = swp2(x1), x2s = swp2(x2);
            v[jb + k]         = fma2_(Ax, x1, fma2_(Ay, x1s, fma2_(Bx, x2, mul2_(By, x2s))));
            v[jb + k + M / 2] = fma2_(Cx, x1, fma2_(Cy, x1s, fma2_(Dx, x2, mul2_(Dy, x2s))));
        }
    }
}

// ====== m=32 diag, strided: partner via shfl_xor(16), coeffs lane-indexed ====
__device__ __forceinline__ void sdiag32_p(u64 (&v)[16], const float2* __restrict__ ab,
                                          int lane) {
    const bool hi = lane >= 16;
    const int k = lane & 15;
    const float2 P = ab[(hi ? 32 : 0) + k];   // A or C
    const float2 Q = ab[(hi ? 48 : 16) + k];  // B or D
#pragma unroll
    for (int j = 0; j < 16; ++j) {
        u64 pxq = __shfl_xor_sync(0xffffffffu, v[j], 16);
        float2 own = upk2(v[j]), px = upk2(pxq);
        float2 x1 = hi ? px : own;
        float2 x2 = hi ? own : px;
        float yr = P.x * x1.x - P.y * x1.y + Q.x * x2.x - Q.y * x2.y;
        float yi = P.x * x1.y + P.y * x1.x + Q.x * x2.y + Q.y * x2.x;
        v[j] = pk2(yr, yi);
    }
}

// ====== large diag M=64..512, strided: register-local pairing ================
template<int M>
__device__ __forceinline__ void sdiag_p(u64 (&v)[16], const float2* __restrict__ ab,
                                        int lane) {
    constexpr int M32 = M / 32, H32 = M / 64, HS = M / 2;
#pragma unroll
    for (int j = 0; j < 16; ++j) {
        int jm = j & (M32 - 1);
        if (jm < H32) {
            int j2 = j + H32;
            int k = lane + 32 * jm;
            float2 A = ab[k], B = ab[HS + k], C = ab[M + k], D = ab[M + HS + k];
            float2 x1 = upk2(v[j]), x2 = upk2(v[j2]);
            float yr1 = A.x * x1.x - A.y * x1.y + B.x * x2.x - B.y * x2.y;
            float yi1 = A.x * x1.y + A.y * x1.x + B.x * x2.y + B.y * x2.x;
            float yr2 = C.x * x1.x - C.y * x1.y + D.x * x2.x - D.y * x2.y;
            float yi2 = C.x * x1.y + C.y * x1.x + D.x * x2.y + D.y * x2.x;
            v[j]  = pk2(yr1, yi1);
            v[j2] = pk2(yr2, yi2);
        }
    }
}

// ====== m=1024 diag: cross-warp partner exchange via smem ====================
__device__ __forceinline__ void sdiag1024_p(u64 (&v)[16], u64* __restrict__ pl,
                                            const float2* __restrict__ ab,
                                            int lane, int w, int ibase, int barid) {
    __syncwarp();
#pragma unroll
    for (int j = 0; j < 16; ++j) pl[skew(ibase + 32 * j)] = v[j];
    rowbar(barid);
#pragma unroll
    for (int j = 0; j < 16; ++j) {
        int i = ibase + 32 * j;
        u64 pxq = pl[skew(i ^ 512)];
        int k = lane + 32 * j;                   // i & 511
        float2 P = ab[(w ? 1024 : 0) + k];       // A or C
        float2 Q = ab[(w ? 1536 : 512) + k];     // B or D
        float2 own = upk2(v[j]), px = upk2(pxq);
        float2 x1 = w ? px : own;
        float2 x2 = w ? own : px;
        float yr = P.x * x1.x - P.y * x1.y + Q.x * x2.x - Q.y * x2.y;
        float yi = P.x * x1.y + P.y * x1.x + Q.x * x2.y + Q.y * x2.x;
        v[j] = pk2(yr, yi);
    }
    rowbar(barid);
}

// ============================ layout transposes ==============================
__device__ __forceinline__ void tr_s2c_r(float (&v)[16], float* __restrict__ fpl,
                                         int t, int ibase) {
    __syncwarp();
#pragma unroll
    for (int j = 0; j < 16; ++j) fpl[skew(ibase + 32 * j)] = v[j];
    __syncwarp();
#pragma unroll
    for (int j = 0; j < 16; ++j) v[j] = fpl[skew(16 * t + j)];
}
__device__ __forceinline__ void tr_s2c_p(u64 (&v)[16], u64* __restrict__ pl,
                                         int t, int ibase) {
    __syncwarp();
#pragma unroll
    for (int j = 0; j < 16; ++j) pl[skew(ibase + 32 * j)] = v[j];
    __syncwarp();
#pragma unroll
    for (int j = 0; j < 16; ++j) v[j] = pl[skew(16 * t + j)];
}
__device__ __forceinline__ void tr_c2s_p(u64 (&v)[16], u64* __restrict__ pl,
                                         int t, int ibase) {
    __syncwarp();
#pragma unroll
    for (int j = 0; j < 16; ++j) pl[skew(16 * t + j)] = v[j];
    __syncwarp();
#pragma unroll
    for (int j = 0; j < 16; ++j) v[j] = pl[skew(ibase + 32 * j)];
}

__global__ void __launch_bounds__(RPC * 64, 4)
butterfly_kernel(const float* __restrict__ x,
                 const float* __restrict__ perm_logit,
                 const float* __restrict__ abcd_f,
                 const float* __restrict__ bias,
                 float* __restrict__ out)
{
    __shared__ u64   uplane[RPC][FPAD];   // 16.9 KB
    __shared__ float fplane[RPC][FPAD];   // 8.4 KB (separate: avoids aliasing)
    __shared__ u64   sdup[2][15][8];      // 1.9 KB small-diag packed coeffs

    const int tid  = threadIdx.x;
    const int rowi = tid >> 6;
    const int t    = tid & 63;
    const int w    = t >> 5;
    const int lane = t & 31;
    const int row  = blockIdx.x * RPC + rowi;
    const int ibase = 512 * w + lane;
    const int barid = 1 + rowi;
    u64*   pl  = uplane[rowi];
    float* fpl = fplane[rowi];

    const float2* abcd = reinterpret_cast<const float2*>(abcd_f);

    // ---- packed coefficient table for small diags m=2..16 (both depths) ----
    for (int s = tid; s < 30; s += blockDim.x) {
        int d = s / 15, u = s % 15;
        int M, k, fac;
        if      (u < 1)  { M = 2;  k = u;      fac = 4088; }
        else if (u < 3)  { M = 4;  k = u - 1;  fac = 4080; }
        else if (u < 7)  { M = 8;  k = u - 3;  fac = 4064; }
        else             { M = 16; k = u - 7;  fac = 4032; }
        const float2* ab = abcd + d * TOTAL_AB + fac;
        float2 A = ab[k], B = ab[M / 2 + k], C = ab[M + k], D = ab[M + M / 2 + k];
        u64* o = sdup[d][u];
        o[0] = dup2(A.x); o[1] = pk2(-A.y, A.y);
        o[2] = dup2(B.x); o[3] = pk2(-B.y, B.y);
        o[4] = dup2(C.x); o[5] = pk2(-C.y, C.y);
        o[6] = dup2(D.x); o[7] = pk2(-D.y, D.y);
    }

    // ---- direct contiguous load: thread t owns elements [16t, 16t+16) ----
    float cr[16];
    const float* xr = x + (size_t)row * NN + 16 * t;
#pragma unroll
    for (int it = 0; it < 4; ++it) {
        float4 tv = *reinterpret_cast<const float4*>(xr + 4 * it);
        cr[4 * it + 0] = tv.x;  cr[4 * it + 1] = tv.y;
        cr[4 * it + 2] = tv.z;  cr[4 * it + 3] = tv.w;
    }
    __syncthreads();   // sdup ready

    // ======================= depth 0: perms purely REAL =======================
    {
        const float p0 = sigmoidf_(perm_logit[0]);
        const float p1 = sigmoidf_(perm_logit[1]);
        const float p2 = sigmoidf_(perm_logit[2]);
        perm_small_r<4 >(cr, p0, p1, p2);
        perm_small_r<8 >(cr, p0, p1, p2);
        perm_small_r<16>(cr, p0, p1, p2);
        perm32_pair_r(cr, t & 1, p0, p1, p2);
        sperm_r<64,  true >(cr, fpl, lane, ibase, t, p0, p1, p2);
        sperm_r<128, false>(cr, fpl, lane, ibase, t, p0, p1, p2);
        sperm_r<256, false>(cr, fpl, lane, ibase, t, p0, p1, p2);
        sperm_r<512, false>(cr, fpl, lane, ibase, t, p0, p1, p2);
        sperm1024_r(cr, fpl, lane, w, ibase, barid, p0, p1, p2);
        tr_s2c_r(cr, fpl, t, ibase);   // contiguous for small diags
    }

    // ---- first diag (m=2), imag==0: real -> packed complex (contiguous) ----
    u64 vc[16];
    {
        const u64* abq = reinterpret_cast<const u64*>(abcd + 4088);
        const u64 A = abq[0], B = abq[1], C = abq[2], D = abq[3];
#pragma unroll
        for (int jb = 0; jb < 16; jb += 2) {
            u64 x1 = dup2(cr[jb]), x2 = dup2(cr[jb + 1]);
            vc[jb]     = fma2_(A, x1, mul2_(B, x2));
            vc[jb + 1] = fma2_(C, x1, mul2_(D, x2));
        }
    }
    diag_small_p<4 >(vc, sdup[0] + 1);
    diag_small_p<8 >(vc, sdup[0] + 3);
    diag_small_p<16>(vc, sdup[0] + 7);
    rowbar(barid);                       // float-plane readers done before u64 writes
    tr_c2s_p(vc, pl, t, ibase);          // strided for large diags
    sdiag32_p(vc, abcd + 3968, lane);
    sdiag_p<64 >(vc, abcd + 3840, lane);
    sdiag_p<128>(vc, abcd + 3584, lane);
    sdiag_p<256>(vc, abcd + 3072, lane);
    sdiag_p<512>(vc, abcd + 2048, lane);
    sdiag1024_p(vc, pl, abcd, lane, w, ibase, barid);

    // ======================= depth 1: full packed complex =====================
    {
        const float p0 = sigmoidf_(perm_logit[3]);
        const float p1 = sigmoidf_(perm_logit[4]);
        const float p2 = sigmoidf_(perm_logit[5]);
        const u64 p02 = dup2(p0), q02 = dup2(1.0f - p0);
        const u64 p12 = dup2(p1), q12 = dup2(1.0f - p1);
        const u64 p22 = dup2(p2), q22 = dup2(1.0f - p2);

        tr_s2c_p(vc, pl, t, ibase);      // contiguous for small perms
        perm_small_p<4 >(vc, q02, p02, q12, p12, q22, p22);
        perm_small_p<8 >(vc, q02, p02, q12, p12, q22, p22);
        perm_small_p<16>(vc, q02, p02, q12, p12, q22, p22);
        perm32_pair_p(vc, t & 1, q02, p02, q12, p12, q22, p22);
        sperm_p<64,  true >(vc, pl, lane, ibase, t, q02, p02, q12, p12, q22, p22);
        sperm_p<128, false>(vc, pl, lane, ibase, t, q02, p02, q12, p12, q22, p22);
        sperm_p<256, false>(vc, pl, lane, ibase, t, q02, p02, q12, p12, q22, p22);
        sperm_p<512, false>(vc, pl, lane, ibase, t, q02, p02, q12, p12, q22, p22);
        sperm1024_p(vc, pl, lane, w, ibase, barid, q02, p02, q12, p12, q22, p22);
        tr_s2c_p(vc, pl, t, ibase);      // contiguous for small diags

        const float2* ab1 = abcd + TOTAL_AB;
        diag_small_p<2 >(vc, sdup[1] + 0);
        diag_small_p<4 >(vc, sdup[1] + 1);
        diag_small_p<8 >(vc, sdup[1] + 3);
        diag_small_p<16>(vc, sdup[1] + 7);
        tr_c2s_p(vc, pl, t, ibase);      // strided for large diags
        sdiag32_p(vc, ab1 + 3968, lane);
        sdiag_p<64 >(vc, ab1 + 3840, lane);
        sdiag_p<128>(vc, ab1 + 3584, lane);
        sdiag_p<256>(vc, ab1 + 3072, lane);
        sdiag_p<512>(vc, ab1 + 2048, lane);
        sdiag1024_p(vc, pl, ab1, lane, w, ibase, barid);
    }

    // ---- write back: strided layout is coalesced across lanes ----
    float* orow = out + (size_t)row * NN;
#pragma unroll
    for (int j = 0; j < 16; ++j) {
        int p = ibase + 32 * j;
        orow[p] = upk2(vc[j]).x + bias[p];
    }
}

extern "C" void kernel_launch(void* const* d_in, const int* in_sizes, int n_in,
                              void* d_out, int out_size)
{
    const float* x    = (const float*)d_in[0];
    const float* pl   = (const float*)d_in[1];
    const float* abcd = (const float*)d_in[2];
    const float* b    = (const float*)d_in[3];
    float* out = (float*)d_out;

    int rows = in_sizes[0] / NN;           // 16384
    int ctas = rows / RPC;                 // 8192
    butterfly_kernel<<<ctas, RPC * 64>>>(x, pl, abcd, b, out);
}